// round 16
// baseline (speedup 1.0000x reference)
#include <cuda_runtime.h>
#include <cuda_fp16.h>
#include <math.h>
#include <stdint.h>

#define BB 4
#define SS 4096
#define DD 768
#define FFD 3072
#define HH 12
#define WW 128
#define NC (SS / WW)
#define ROWS (BB * SS)

// GEMM tile: 128x128, 8 warps (warp tile 32x64), BK=64, 3-stage cp.async
#define GBM 128
#define GBN 128
#define GBK 64
#define GSTAGES 3
#define HSTRIDE 72
#define TILE_STAGE (128 * HSTRIDE)

// attention smem layout: Q(128) + K(192) + V(192) rows, stride AQSTRIDE
#define AQSTRIDE 72
#define KS_OFF (128 * AQSTRIDE)
#define VS_OFF (KS_OFF + 192 * AQSTRIDE)
#define ATTN_SMEM ((VS_OFF + 192 * AQSTRIDE) * 2)

// ---------------------------------------------------------------------------
// Scratch (device globals; no runtime allocation allowed)
// ---------------------------------------------------------------------------
__device__ float  g_x[ROWS * DD];
__device__ float  g_xb[ROWS * DD];
__device__ float  g_a[ROWS * DD];
__device__ __half g_xin16[ROWS * DD];
__device__ __half g_xb16[ROWS * DD];
__device__ __half g_h16[(size_t)ROWS * FFD];
__device__ __half g_qkv16[(size_t)ROWS * 3 * DD];
__device__ __half g_Wqkv[4 * 3 * DD * DD];
__device__ __half g_W1T[4 * DD * FFD];
__device__ __half g_W2T[4 * DD * FFD];
__device__ float  g_bqkv[4 * 3 * DD];

// ---------------------------------------------------------------------------
// Helpers
// ---------------------------------------------------------------------------
__device__ __forceinline__ uint32_t smem_u32(const void* p) {
    uint32_t a;
    asm("{ .reg .u64 t; cvta.to.shared.u64 t, %1; cvt.u32.u64 %0, t; }"
        : "=r"(a) : "l"(p));
    return a;
}
__device__ __forceinline__ void cp_async16(uint32_t dst, const void* src) {
    asm volatile("cp.async.cg.shared.global [%0], [%1], 16;"
                 :: "r"(dst), "l"(src));
}
__device__ __forceinline__ void cp_commit() {
    asm volatile("cp.async.commit_group;" ::: "memory");
}
template <int N>
__device__ __forceinline__ void cp_wait() {
    asm volatile("cp.async.wait_group %0;" :: "n"(N) : "memory");
}
__device__ __forceinline__ void mma_f16(float* c, const uint32_t* a,
                                        const uint32_t* b) {
    asm volatile(
        "mma.sync.aligned.m16n8k16.row.col.f32.f16.f16.f32 "
        "{%0,%1,%2,%3}, {%4,%5,%6,%7}, {%8,%9}, {%0,%1,%2,%3};"
        : "+f"(c[0]), "+f"(c[1]), "+f"(c[2]), "+f"(c[3])
        : "r"(a[0]), "r"(a[1]), "r"(a[2]), "r"(a[3]), "r"(b[0]), "r"(b[1]));
}
__device__ __forceinline__ void ldsm_x4(uint32_t* r, uint32_t addr) {
    asm volatile("ldmatrix.sync.aligned.m8n8.x4.shared.b16 {%0,%1,%2,%3}, [%4];"
                 : "=r"(r[0]), "=r"(r[1]), "=r"(r[2]), "=r"(r[3]) : "r"(addr));
}
__device__ __forceinline__ void ldsm_x4_t(uint32_t* r, uint32_t addr) {
    asm volatile("ldmatrix.sync.aligned.m8n8.x4.trans.shared.b16 "
                 "{%0,%1,%2,%3}, [%4];"
                 : "=r"(r[0]), "=r"(r[1]), "=r"(r[2]), "=r"(r[3]) : "r"(addr));
}
__device__ __forceinline__ uint32_t h2u(float x, float y) {
    __half2 h = __floats2half2_rn(x, y);
    return *reinterpret_cast<uint32_t*>(&h);
}

// ---------------------------------------------------------------------------
// Fused QKV weight transpose: 12 slabs (4 layers x {q,k,v}), q scaled 0.125.
// ---------------------------------------------------------------------------
__global__ __launch_bounds__(256)
void transpose_qkv(const float* __restrict__ Wq, const float* __restrict__ Wk,
                   const float* __restrict__ Wv, __half* __restrict__ dst)
{
    __shared__ float t[32][33];
    const int z = blockIdx.z;
    const int l = z / 3, m = z % 3;
    const float* src = (m == 0 ? Wq : (m == 1 ? Wk : Wv)) + (size_t)l * DD * DD;
    __half* d = dst + (size_t)l * 3 * DD * DD + (size_t)m * DD * DD;
    const float scale = (m == 0) ? 0.125f : 1.0f;
    const int kb = blockIdx.y * 32, nb = blockIdx.x * 32;
    const int tx = threadIdx.x, ty = threadIdx.y;
#pragma unroll
    for (int i = 0; i < 32; i += 8)
        t[ty + i][tx] = src[(size_t)(kb + ty + i) * DD + nb + tx];
    __syncthreads();
#pragma unroll
    for (int i = 0; i < 32; i += 8)
        d[(size_t)(nb + ty + i) * DD + kb + tx] =
            __float2half_rn(t[tx][ty + i] * scale);
}

// Generic weight transpose for W1/W2: src [L,K,N] fp32 -> dst [L,N,K] fp16.
__global__ __launch_bounds__(256)
void transpose_w(const float* __restrict__ src, __half* __restrict__ dst,
                 int K, int N, size_t l_stride)
{
    __shared__ float t[32][33];
    const int l = blockIdx.z;
    src += (size_t)l * K * N;
    dst += (size_t)l * l_stride;
    const int kb = blockIdx.y * 32, nb = blockIdx.x * 32;
    const int tx = threadIdx.x, ty = threadIdx.y;
#pragma unroll
    for (int i = 0; i < 32; i += 8)
        t[ty + i][tx] = src[(size_t)(kb + ty + i) * N + nb + tx];
    __syncthreads();
#pragma unroll
    for (int i = 0; i < 32; i += 8)
        dst[(size_t)(nb + ty + i) * K + kb + tx] = __float2half_rn(t[tx][ty + i]);
}

// fp32 -> fp16 convert (for initial x)
__global__ __launch_bounds__(256)
void f2h_kernel(const float* __restrict__ src, __half* __restrict__ dst, int n)
{
    int i = (blockIdx.x * 256 + threadIdx.x) * 4;
    if (i < n) {
        float4 v = *reinterpret_cast<const float4*>(src + i);
        *reinterpret_cast<__half2*>(dst + i) = __floats2half2_rn(v.x, v.y);
        *reinterpret_cast<__half2*>(dst + i + 2) = __floats2half2_rn(v.z, v.w);
    }
}

// concat qkv bias (bq pre-scaled by 0.125)
__global__ __launch_bounds__(256)
void prep_bias(const float* __restrict__ bq, const float* __restrict__ bk,
               const float* __restrict__ bv, float* __restrict__ out)
{
    int i = blockIdx.x * 256 + threadIdx.x;
    if (i >= 4 * 3 * DD) return;
    int l = i / (3 * DD), r = i % (3 * DD);
    float v;
    if (r < DD) v = bq[l * DD + r] * 0.125f;
    else if (r < 2 * DD) v = bk[l * DD + r - DD];
    else v = bv[l * DD + r - 2 * DD];
    out[i] = v;
}

// ---------------------------------------------------------------------------
// fp16 mma.sync GEMM (R15-proven, unchanged).
// ---------------------------------------------------------------------------
__global__ __launch_bounds__(256, 2)
void gemm_f16(const __half* __restrict__ A, const __half* __restrict__ BT,
              const float* __restrict__ bias, const float* __restrict__ Rf,
              float* __restrict__ Cf, __half* __restrict__ Ch,
              int M, int N, int K, int relu)
{
    extern __shared__ __half hsm[];
    __half* As = hsm;
    __half* Bs = hsm + GSTAGES * TILE_STAGE;

    const int tid = threadIdx.x;
    const int wid = tid >> 5, lane = tid & 31;
    const int warp_m = wid >> 1;
    const int warp_n = wid & 1;
    const int g = lane >> 2;
    const int t4 = lane & 3;

    const int brow = blockIdx.y, bcol = blockIdx.x;
    const __half* Abase = A + (size_t)brow * GBM * K;
    const __half* Bbase = BT + (size_t)bcol * GBN * K;

    const uint32_t AsU = smem_u32(As);
    const uint32_t BsU = smem_u32(Bs);

    const int nk = K / GBK;

    auto stage = [&](int s, int bufi) {
        const int k0 = s * GBK;
        const uint32_t off = (uint32_t)(bufi * TILE_STAGE) * 2u;
#pragma unroll
        for (int i = 0; i < 4; i++) {
            int id = tid + i * 256;
            int r = id >> 3, c8 = id & 7;
            cp_async16(AsU + off + (uint32_t)(r * HSTRIDE + c8 * 8) * 2u,
                       Abase + (size_t)r * K + k0 + c8 * 8);
        }
#pragma unroll
        for (int i = 0; i < 4; i++) {
            int id = tid + i * 256;
            int r = id >> 3, c8 = id & 7;
            cp_async16(BsU + off + (uint32_t)(r * HSTRIDE + c8 * 8) * 2u,
                       Bbase + (size_t)r * K + k0 + c8 * 8);
        }
        cp_commit();
    };

    float acc[2][8][4];
#pragma unroll
    for (int mt = 0; mt < 2; mt++)
#pragma unroll
        for (int nt = 0; nt < 8; nt++)
#pragma unroll
            for (int j = 0; j < 4; j++) acc[mt][nt][j] = 0.0f;

#pragma unroll
    for (int s = 0; s < GSTAGES - 1; s++) {
        if (s < nk) stage(s, s); else cp_commit();
    }

    const uint32_t lrow = (uint32_t)(lane & 15) * (HSTRIDE * 2);
    const uint32_t lcol = (uint32_t)(lane >> 4) * 16;

    int rbuf = 0;
    int pbuf = GSTAGES - 1;

    for (int ks = 0; ks < nk; ks++) {
        cp_wait<GSTAGES - 2>();
        __syncthreads();

        if (ks + GSTAGES - 1 < nk) stage(ks + GSTAGES - 1, pbuf);
        else cp_commit();
        if (++pbuf == GSTAGES) pbuf = 0;

        const uint32_t abuf = AsU + (uint32_t)(rbuf * TILE_STAGE) * 2u;
        const uint32_t bbuf = BsU + (uint32_t)(rbuf * TILE_STAGE) * 2u;
        if (++rbuf == GSTAGES) rbuf = 0;

#pragma unroll
        for (int kk = 0; kk < 4; kk++) {
            const uint32_t co = (uint32_t)kk * 32 + lcol;
            uint32_t a[2][4];
#pragma unroll
            for (int mt = 0; mt < 2; mt++)
                ldsm_x4(a[mt], abuf + (uint32_t)(warp_m * 32 + mt * 16) *
                                       (HSTRIDE * 2) + lrow + co);
            uint32_t b[8][2];
#pragma unroll
            for (int np = 0; np < 4; np++) {
                uint32_t tr[4];
                ldsm_x4(tr, bbuf + (uint32_t)(warp_n * 64 + np * 16) *
                                    (HSTRIDE * 2) + lrow + co);
                b[np * 2][0] = tr[0]; b[np * 2 + 1][0] = tr[1];
                b[np * 2][1] = tr[2]; b[np * 2 + 1][1] = tr[3];
            }
#pragma unroll
            for (int mt = 0; mt < 2; mt++)
#pragma unroll
                for (int nt = 0; nt < 8; nt++)
                    mma_f16(acc[mt][nt], a[mt], b[nt]);
        }
    }

#pragma unroll
    for (int mt = 0; mt < 2; mt++) {
        const int r0 = brow * GBM + warp_m * 32 + mt * 16 + g;
#pragma unroll
        for (int nt = 0; nt < 8; nt++) {
            const int cb = bcol * GBN + warp_n * 64 + nt * 8 + t4 * 2;
            const float b0 = bias[cb], b1 = bias[cb + 1];
            float v0 = acc[mt][nt][0] + b0;
            float v1 = acc[mt][nt][1] + b1;
            float v2 = acc[mt][nt][2] + b0;
            float v3 = acc[mt][nt][3] + b1;
            if (relu) {
                v0 = fmaxf(v0, 0.f); v1 = fmaxf(v1, 0.f);
                v2 = fmaxf(v2, 0.f); v3 = fmaxf(v3, 0.f);
            }
            if (Rf) {
                float2 r0v = *reinterpret_cast<const float2*>(
                    Rf + (size_t)r0 * N + cb);
                float2 r1v = *reinterpret_cast<const float2*>(
                    Rf + (size_t)(r0 + 8) * N + cb);
                v0 += r0v.x; v1 += r0v.y;
                v2 += r1v.x; v3 += r1v.y;
            }
            if (Cf) {
                *reinterpret_cast<float2*>(Cf + (size_t)r0 * N + cb) =
                    make_float2(v0, v1);
                *reinterpret_cast<float2*>(Cf + (size_t)(r0 + 8) * N + cb) =
                    make_float2(v2, v3);
            }
            if (Ch) {
                *reinterpret_cast<__half2*>(Ch + (size_t)r0 * N + cb) =
                    __floats2half2_rn(v0, v1);
                *reinterpret_cast<__half2*>(Ch + (size_t)(r0 + 8) * N + cb) =
                    __floats2half2_rn(v2, v3);
            }
        }
    }
}

// ---------------------------------------------------------------------------
// Flash sliding-window attention; mask-skip + rescale-skip fast paths.
// ---------------------------------------------------------------------------
__global__ __launch_bounds__(256, 2)
void attn_mma(const __half* __restrict__ qkv, const float* __restrict__ res,
              float* __restrict__ out)
{
    extern __shared__ __half ash[];
    __half* Ks = ash + KS_OFF;
    __half* Vs = ash + VS_OFF;

    const int c = blockIdx.x, h = blockIdx.y, b = blockIdx.z;
    const int tid = threadIdx.x;
    const int w = tid >> 5, lane = tid & 31;
    const int g = lane >> 2, t4 = lane & 3;
    const int qoff = h * 64, koff = DD + h * 64, voff = 2 * DD + h * 64;
    const int cbase = c * 128 - 128;

    const uint32_t QsU = smem_u32(ash);
    const uint32_t KsU = smem_u32(Ks);
    const uint32_t VsU = smem_u32(Vs);

#pragma unroll
    for (int i = 0; i < 4; i++) {
        int id = tid + i * 256;
        int r = id >> 3, ch = id & 7;
        uint4 v = *reinterpret_cast<const uint4*>(
            qkv + (size_t)(b * SS + c * 128 + r) * (3 * DD) + qoff + ch * 8);
        *reinterpret_cast<uint4*>(&ash[r * AQSTRIDE + ch * 8]) = v;
    }
    __syncthreads();

    const uint32_t lrow = (uint32_t)(lane & 15) * (AQSTRIDE * 2);
    const uint32_t lcol = (uint32_t)(lane >> 4) * 16;
    uint32_t qa[4][4];
#pragma unroll
    for (int ks = 0; ks < 4; ks++)
        ldsm_x4(qa[ks], QsU + (uint32_t)(w * 16) * (AQSTRIDE * 2) + lrow +
                        (uint32_t)ks * 32 + lcol);

    float o[8][4];
#pragma unroll
    for (int ch = 0; ch < 8; ch++)
#pragma unroll
        for (int j = 0; j < 4; j++) o[ch][j] = 0.0f;
    float m0 = -1e30f, m1 = -1e30f, l0 = 0.0f, l1 = 0.0f;
    const int qi0 = w * 16 + g, qi1 = qi0 + 8;

    for (int t = 0; t < 2; t++) {
        if (t) __syncthreads();
        const int kw0 = t * 192;
#pragma unroll
        for (int i = 0; i < 6; i++) {
            int id = tid + i * 256;
            int r = id >> 3, ch = id & 7;
            int kpos = cbase + kw0 + r;
            uint4 kv = make_uint4(0, 0, 0, 0), vv = make_uint4(0, 0, 0, 0);
            if (kpos >= 0 && kpos < SS) {
                const __half* rp = qkv + (size_t)(b * SS + kpos) * (3 * DD);
                kv = *reinterpret_cast<const uint4*>(rp + koff + ch * 8);
                vv = *reinterpret_cast<const uint4*>(rp + voff + ch * 8);
            }
            *reinterpret_cast<uint4*>(&Ks[r * AQSTRIDE + ch * 8]) = kv;
            *reinterpret_cast<uint4*>(&Vs[r * AQSTRIDE + ch * 8]) = vv;
        }
        __syncthreads();

        const int jb_lo = (t == 0) ? w : 12;
        const int jb_hi = (t == 0) ? 11 : (w + 16);

        for (int jb = jb_lo; jb <= jb_hi; jb++) {
            const int j0 = jb * 16 - kw0;
            float s0[4] = {0.f, 0.f, 0.f, 0.f};
            float s1[4] = {0.f, 0.f, 0.f, 0.f};
#pragma unroll
            for (int ks = 0; ks < 4; ks++) {
                uint32_t kb[4];
                ldsm_x4(kb, KsU + (uint32_t)j0 * (AQSTRIDE * 2) + lrow +
                            (uint32_t)ks * 32 + lcol);
                uint32_t b0[2] = {kb[0], kb[2]};
                uint32_t b1[2] = {kb[1], kb[3]};
                mma_f16(s0, qa[ks], b0);
                mma_f16(s1, qa[ks], b1);
            }
            // mask only boundary blocks (per-warp uniform test)
            {
                const int kpos0 = cbase + jb * 16;
                const bool interior = (jb > w) && (jb < w + 16) &&
                                      ((unsigned)kpos0 <= (unsigned)(SS - 16));
                if (!interior) {
                    const int cw = jb * 16 + 2 * t4;
                    auto mk = [&](float s, int cwi, int qi) -> float {
                        unsigned d = (unsigned)(cwi - qi);
                        int kp = cbase + cwi;
                        return (d <= 256u && kp >= 0 && kp < SS) ? s : -3.0e38f;
                    };
                    s0[0] = mk(s0[0], cw,     qi0); s0[1] = mk(s0[1], cw + 1, qi0);
                    s0[2] = mk(s0[2], cw,     qi1); s0[3] = mk(s0[3], cw + 1, qi1);
                    s1[0] = mk(s1[0], cw + 8, qi0); s1[1] = mk(s1[1], cw + 9, qi0);
                    s1[2] = mk(s1[2], cw + 8, qi1); s1[3] = mk(s1[3], cw + 9, qi1);
                }
            }
            float bm0 = fmaxf(fmaxf(s0[0], s0[1]), fmaxf(s1[0], s1[1]));
            float bm1 = fmaxf(fmaxf(s0[2], s0[3]), fmaxf(s1[2], s1[3]));
            bm0 = fmaxf(bm0, __shfl_xor_sync(0xffffffffu, bm0, 1));
            bm0 = fmaxf(bm0, __shfl_xor_sync(0xffffffffu, bm0, 2));
            bm1 = fmaxf(bm1, __shfl_xor_sync(0xffffffffu, bm1, 1));
            bm1 = fmaxf(bm1, __shfl_xor_sync(0xffffffffu, bm1, 2));
            float mn0 = fmaxf(m0, bm0), mn1 = fmaxf(m1, bm1);
            const bool allsame = __all_sync(0xffffffffu,
                                            (mn0 == m0) && (mn1 == m1));
            float sc0 = 1.0f, sc1 = 1.0f;
            if (!allsame) {
                sc0 = __expf(m0 - mn0);
                sc1 = __expf(m1 - mn1);
            }
            m0 = mn0; m1 = mn1;
            float p00 = __expf(s0[0] - mn0), p01 = __expf(s0[1] - mn0);
            float p10 = __expf(s0[2] - mn1), p11 = __expf(s0[3] - mn1);
            float p02 = __expf(s1[0] - mn0), p03 = __expf(s1[1] - mn0);
            float p12 = __expf(s1[2] - mn1), p13 = __expf(s1[3] - mn1);
            float rs0 = (p00 + p01) + (p02 + p03);
            float rs1 = (p10 + p11) + (p12 + p13);
            rs0 += __shfl_xor_sync(0xffffffffu, rs0, 1);
            rs0 += __shfl_xor_sync(0xffffffffu, rs0, 2);
            rs1 += __shfl_xor_sync(0xffffffffu, rs1, 1);
            rs1 += __shfl_xor_sync(0xffffffffu, rs1, 2);
            l0 = l0 * sc0 + rs0;
            l1 = l1 * sc1 + rs1;

            uint32_t pa[4];
            pa[0] = h2u(p00, p01);
            pa[1] = h2u(p10, p11);
            pa[2] = h2u(p02, p03);
            pa[3] = h2u(p12, p13);

            uint32_t vb[8][2];
#pragma unroll
            for (int p = 0; p < 4; p++) {
                uint32_t tr[4];
                ldsm_x4_t(tr, VsU + (uint32_t)j0 * (AQSTRIDE * 2) + lrow +
                              (uint32_t)p * 32 + lcol);
                vb[p * 2][0] = tr[0]; vb[p * 2][1] = tr[1];
                vb[p * 2 + 1][0] = tr[2]; vb[p * 2 + 1][1] = tr[3];
            }

            if (allsame) {
#pragma unroll
                for (int ch = 0; ch < 8; ch++)
                    mma_f16(o[ch], pa, vb[ch]);
            } else {
#pragma unroll
                for (int ch = 0; ch < 8; ch++) {
                    o[ch][0] *= sc0; o[ch][1] *= sc0;
                    o[ch][2] *= sc1; o[ch][3] *= sc1;
                    mma_f16(o[ch], pa, vb[ch]);
                }
            }
        }
    }

    const float inv0 = 1.0f / l0, inv1 = 1.0f / l1;
    const size_t row0 = (size_t)(b * SS + c * 128 + w * 16 + g) * DD + h * 64;
    float* op0 = out + row0;
    float* op1 = op0 + 8 * DD;
    const float* rp0 = res + row0;
    const float* rp1 = rp0 + 8 * DD;
#pragma unroll
    for (int ch = 0; ch < 8; ch++) {
        float2 a0 = *reinterpret_cast<const float2*>(rp0 + ch * 8 + 2 * t4);
        float2 a1 = *reinterpret_cast<const float2*>(rp1 + ch * 8 + 2 * t4);
        *reinterpret_cast<float2*>(op0 + ch * 8 + 2 * t4) =
            make_float2(o[ch][0] * inv0 + a0.x, o[ch][1] * inv0 + a0.y);
        *reinterpret_cast<float2*>(op1 + ch * 8 + 2 * t4) =
            make_float2(o[ch][2] * inv1 + a1.x, o[ch][3] * inv1 + a1.y);
    }
}

// ---------------------------------------------------------------------------
// LayerNorm, single-pass (sum + sumsq in one fused reduction).
// 192 threads, 1 row per CTA. Var = E[x^2] - mean^2.
// ---------------------------------------------------------------------------
__global__ __launch_bounds__(192)
void ln_kernel(const float* __restrict__ x,
               const float* __restrict__ g, const float* __restrict__ bt,
               float* __restrict__ out, __half* __restrict__ out16)
{
    __shared__ float sh[12];
    const int row = blockIdx.x;
    const int tid = threadIdx.x;
    const int lane = tid & 31, wp = tid >> 5;   // 6 warps

    float4 v = reinterpret_cast<const float4*>(x + (size_t)row * DD)[tid];

    float s = (v.x + v.y) + (v.z + v.w);
    float q = (v.x * v.x + v.y * v.y) + (v.z * v.z + v.w * v.w);
#pragma unroll
    for (int o = 16; o; o >>= 1) {
        s += __shfl_xor_sync(0xffffffffu, s, o);
        q += __shfl_xor_sync(0xffffffffu, q, o);
    }
    if (lane == 0) { sh[wp * 2] = s; sh[wp * 2 + 1] = q; }
    __syncthreads();
    float t = (lane < 12) ? sh[lane] : 0.0f;
    t += __shfl_xor_sync(0xffffffffu, t, 2);
    t += __shfl_xor_sync(0xffffffffu, t, 4);
    t += __shfl_xor_sync(0xffffffffu, t, 8);
    const float s_tot = __shfl_sync(0xffffffffu, t, 0);
    const float q_tot = __shfl_sync(0xffffffffu, t, 1);

    const float mean = s_tot * (1.0f / (float)DD);
    const float var  = q_tot * (1.0f / (float)DD) - mean * mean;
    const float inv  = rsqrtf(var + 1e-5f);

    float4 gv = reinterpret_cast<const float4*>(g)[tid];
    float4 bv = reinterpret_cast<const float4*>(bt)[tid];
    float o0 = (v.x - mean) * inv * gv.x + bv.x;
    float o1 = (v.y - mean) * inv * gv.y + bv.y;
    float o2 = (v.z - mean) * inv * gv.z + bv.z;
    float o3 = (v.w - mean) * inv * gv.w + bv.w;

    reinterpret_cast<float4*>(out + (size_t)row * DD)[tid] =
        make_float4(o0, o1, o2, o3);
    uint2 hu;
    hu.x = h2u(o0, o1);
    hu.y = h2u(o2, o3);
    reinterpret_cast<uint2*>(out16 + (size_t)row * DD)[tid] = hu;
}

// ---------------------------------------------------------------------------
// Host driver
// ---------------------------------------------------------------------------
extern "C" void kernel_launch(void* const* d_in, const int* in_sizes, int n_in,
                              void* d_out, int out_size)
{
    (void)in_sizes; (void)n_in; (void)out_size;

    const float* x0  = (const float*)d_in[0];
    const float* Wq  = (const float*)d_in[1];
    const float* bq  = (const float*)d_in[2];
    const float* Wk  = (const float*)d_in[3];
    const float* bk  = (const float*)d_in[4];
    const float* Wv  = (const float*)d_in[5];
    const float* bv  = (const float*)d_in[6];
    const float* W1  = (const float*)d_in[7];
    const float* b1  = (const float*)d_in[8];
    const float* W2  = (const float*)d_in[9];
    const float* b2  = (const float*)d_in[10];
    const float* g1  = (const float*)d_in[11];
    const float* be1 = (const float*)d_in[12];
    const float* g2  = (const float*)d_in[13];
    const float* be2 = (const float*)d_in[14];

    float* outp = (float*)d_out;

    float *xb_run, *xbb, *ab, *bqkv;
    __half *xin16, *xb16, *h16, *qkv16, *wqkv, *w1t, *w2t;
    cudaGetSymbolAddress((void**)&xb_run, g_x);
    cudaGetSymbolAddress((void**)&xbb, g_xb);
    cudaGetSymbolAddress((void**)&ab, g_a);
    cudaGetSymbolAddress((void**)&bqkv, g_bqkv);
    cudaGetSymbolAddress((void**)&xin16, g_xin16);
    cudaGetSymbolAddress((void**)&xb16, g_xb16);
    cudaGetSymbolAddress((void**)&h16, g_h16);
    cudaGetSymbolAddress((void**)&qkv16, g_qkv16);
    cudaGetSymbolAddress((void**)&wqkv, g_Wqkv);
    cudaGetSymbolAddress((void**)&w1t, g_W1T);
    cudaGetSymbolAddress((void**)&w2t, g_W2T);

    cudaFuncSetAttribute(attn_mma, cudaFuncAttributeMaxDynamicSharedMemorySize,
                         ATTN_SMEM);
    const int gemm_smem = 2 * GSTAGES * TILE_STAGE * (int)sizeof(__half);
    cudaFuncSetAttribute(gemm_f16, cudaFuncAttributeMaxDynamicSharedMemorySize,
                         gemm_smem);

    dim3 tb(32, 8);
    const size_t qkvL = (size_t)3 * DD * DD;
    dim3 gQKV(3 * DD / GBN, ROWS / GBM);
    dim3 gD(DD / GBN, ROWS / GBM);
    dim3 gF(FFD / GBN, ROWS / GBM);
    dim3 gA(NC, HH, BB);

    transpose_qkv<<<dim3(DD / 32, DD / 32, 12), tb>>>(Wq, Wk, Wv, wqkv);
    prep_bias<<<(4 * 3 * DD + 255) / 256, 256>>>(bq, bk, bv, bqkv);
    f2h_kernel<<<(ROWS * DD / 4 + 255) / 256, 256>>>(x0, xin16, ROWS * DD);

    gemm_f16<<<gQKV, 256, gemm_smem>>>(xin16, wqkv, bqkv, (const float*)0,
                                       (float*)0, qkv16, ROWS, 3 * DD, DD, 0);

    transpose_w<<<dim3(FFD / 32, DD / 32, 4), tb>>>(W1, w1t, DD, FFD,
                                                    (size_t)DD * FFD);
    transpose_w<<<dim3(DD / 32, FFD / 32, 4), tb>>>(W2, w2t, FFD, DD,
                                                    (size_t)DD * FFD);

    const float* xc = x0;
    for (int l = 0; l < 4; l++) {
        if (l > 0) {
            gemm_f16<<<gQKV, 256, gemm_smem>>>(xin16, wqkv + l * qkvL,
                                               bqkv + l * 3 * DD,
                                               (const float*)0,
                                               (float*)0, qkv16,
                                               ROWS, 3 * DD, DD, 0);
        }

        attn_mma<<<gA, 256, ATTN_SMEM>>>(qkv16, xc, ab);

        ln_kernel<<<ROWS, 192>>>(ab, g1 + l * DD, be1 + l * DD, xbb, xb16);

        gemm_f16<<<gF, 256, gemm_smem>>>(xb16, w1t + (size_t)l * DD * FFD,
                                         b1 + l * FFD, (const float*)0,
                                         (float*)0, h16, ROWS, FFD, DD, 1);
        gemm_f16<<<gD, 256, gemm_smem>>>(h16, w2t + (size_t)l * DD * FFD,
                                         b2 + l * DD, xbb,
                                         ab, (__half*)0, ROWS, DD, FFD, 0);

        float* xdst = (l == 3) ? outp : xb_run;
        ln_kernel<<<ROWS, 192>>>(ab, g2 + l * DD, be2 + l * DD, xdst, xin16);

        xc = xb_run;
    }
}

// round 17
// speedup vs baseline: 1.0110x; 1.0110x over previous
#include <cuda_runtime.h>
#include <cuda_fp16.h>
#include <math.h>
#include <stdint.h>

#define BB 4
#define SS 4096
#define DD 768
#define FFD 3072
#define HH 12
#define WW 128
#define NC (SS / WW)
#define ROWS (BB * SS)

// GEMM tile: 128x128, 8 warps (warp tile 32x64), BK=64, 3-stage cp.async
#define GBM 128
#define GBN 128
#define GBK 64
#define GSTAGES 3
#define HSTRIDE 72
#define TILE_STAGE (128 * HSTRIDE)

// attention smem layout: Q(128) + K(192) + V(192) rows, stride AQSTRIDE
#define AQSTRIDE 72
#define KS_OFF (128 * AQSTRIDE)
#define VS_OFF (KS_OFF + 192 * AQSTRIDE)
#define ATTN_SMEM ((VS_OFF + 192 * AQSTRIDE) * 2)

// ---------------------------------------------------------------------------
// Scratch (device globals; no runtime allocation allowed)
// ---------------------------------------------------------------------------
__device__ float  g_x[ROWS * DD];
__device__ float  g_xb[ROWS * DD];
__device__ float  g_a[ROWS * DD];
__device__ __half g_xin16[ROWS * DD];
__device__ __half g_xb16[ROWS * DD];
__device__ __half g_h16[(size_t)ROWS * FFD];
__device__ __half g_qkv16[(size_t)ROWS * 3 * DD];
__device__ __half g_Wqkv[4 * 3 * DD * DD];
__device__ __half g_W1T[4 * DD * FFD];
__device__ __half g_W2T[4 * DD * FFD];
__device__ float  g_bqkv[4 * 3 * DD];

// ---------------------------------------------------------------------------
// Helpers
// ---------------------------------------------------------------------------
__device__ __forceinline__ uint32_t smem_u32(const void* p) {
    uint32_t a;
    asm("{ .reg .u64 t; cvta.to.shared.u64 t, %1; cvt.u32.u64 %0, t; }"
        : "=r"(a) : "l"(p));
    return a;
}
__device__ __forceinline__ void cp_async16(uint32_t dst, const void* src) {
    asm volatile("cp.async.cg.shared.global [%0], [%1], 16;"
                 :: "r"(dst), "l"(src));
}
__device__ __forceinline__ void cp_commit() {
    asm volatile("cp.async.commit_group;" ::: "memory");
}
template <int N>
__device__ __forceinline__ void cp_wait() {
    asm volatile("cp.async.wait_group %0;" :: "n"(N) : "memory");
}
__device__ __forceinline__ void mma_f16(float* c, const uint32_t* a,
                                        const uint32_t* b) {
    asm volatile(
        "mma.sync.aligned.m16n8k16.row.col.f32.f16.f16.f32 "
        "{%0,%1,%2,%3}, {%4,%5,%6,%7}, {%8,%9}, {%0,%1,%2,%3};"
        : "+f"(c[0]), "+f"(c[1]), "+f"(c[2]), "+f"(c[3])
        : "r"(a[0]), "r"(a[1]), "r"(a[2]), "r"(a[3]), "r"(b[0]), "r"(b[1]));
}
__device__ __forceinline__ void ldsm_x4(uint32_t* r, uint32_t addr) {
    asm volatile("ldmatrix.sync.aligned.m8n8.x4.shared.b16 {%0,%1,%2,%3}, [%4];"
                 : "=r"(r[0]), "=r"(r[1]), "=r"(r[2]), "=r"(r[3]) : "r"(addr));
}
__device__ __forceinline__ void ldsm_x4_t(uint32_t* r, uint32_t addr) {
    asm volatile("ldmatrix.sync.aligned.m8n8.x4.trans.shared.b16 "
                 "{%0,%1,%2,%3}, [%4];"
                 : "=r"(r[0]), "=r"(r[1]), "=r"(r[2]), "=r"(r[3]) : "r"(addr));
}
__device__ __forceinline__ uint32_t h2u(float x, float y) {
    __half2 h = __floats2half2_rn(x, y);
    return *reinterpret_cast<uint32_t*>(&h);
}

// ---------------------------------------------------------------------------
// Fused QKV weight transpose: 12 slabs (4 layers x {q,k,v}), q scaled 0.125.
// ---------------------------------------------------------------------------
__global__ __launch_bounds__(256)
void transpose_qkv(const float* __restrict__ Wq, const float* __restrict__ Wk,
                   const float* __restrict__ Wv, __half* __restrict__ dst)
{
    __shared__ float t[32][33];
    const int z = blockIdx.z;
    const int l = z / 3, m = z % 3;
    const float* src = (m == 0 ? Wq : (m == 1 ? Wk : Wv)) + (size_t)l * DD * DD;
    __half* d = dst + (size_t)l * 3 * DD * DD + (size_t)m * DD * DD;
    const float scale = (m == 0) ? 0.125f : 1.0f;
    const int kb = blockIdx.y * 32, nb = blockIdx.x * 32;
    const int tx = threadIdx.x, ty = threadIdx.y;
#pragma unroll
    for (int i = 0; i < 32; i += 8)
        t[ty + i][tx] = src[(size_t)(kb + ty + i) * DD + nb + tx];
    __syncthreads();
#pragma unroll
    for (int i = 0; i < 32; i += 8)
        d[(size_t)(nb + ty + i) * DD + kb + tx] =
            __float2half_rn(t[tx][ty + i] * scale);
}

// Generic weight transpose for W1/W2: src [L,K,N] fp32 -> dst [L,N,K] fp16.
__global__ __launch_bounds__(256)
void transpose_w(const float* __restrict__ src, __half* __restrict__ dst,
                 int K, int N, size_t l_stride)
{
    __shared__ float t[32][33];
    const int l = blockIdx.z;
    src += (size_t)l * K * N;
    dst += (size_t)l * l_stride;
    const int kb = blockIdx.y * 32, nb = blockIdx.x * 32;
    const int tx = threadIdx.x, ty = threadIdx.y;
#pragma unroll
    for (int i = 0; i < 32; i += 8)
        t[ty + i][tx] = src[(size_t)(kb + ty + i) * N + nb + tx];
    __syncthreads();
#pragma unroll
    for (int i = 0; i < 32; i += 8)
        dst[(size_t)(nb + ty + i) * K + kb + tx] = __float2half_rn(t[tx][ty + i]);
}

// fp32 -> fp16 convert (for initial x)
__global__ __launch_bounds__(256)
void f2h_kernel(const float* __restrict__ src, __half* __restrict__ dst, int n)
{
    int i = (blockIdx.x * 256 + threadIdx.x) * 4;
    if (i < n) {
        float4 v = *reinterpret_cast<const float4*>(src + i);
        *reinterpret_cast<__half2*>(dst + i) = __floats2half2_rn(v.x, v.y);
        *reinterpret_cast<__half2*>(dst + i + 2) = __floats2half2_rn(v.z, v.w);
    }
}

// concat qkv bias (bq pre-scaled by 0.125)
__global__ __launch_bounds__(256)
void prep_bias(const float* __restrict__ bq, const float* __restrict__ bk,
               const float* __restrict__ bv, float* __restrict__ out)
{
    int i = blockIdx.x * 256 + threadIdx.x;
    if (i >= 4 * 3 * DD) return;
    int l = i / (3 * DD), r = i % (3 * DD);
    float v;
    if (r < DD) v = bq[l * DD + r] * 0.125f;
    else if (r < 2 * DD) v = bk[l * DD + r - DD];
    else v = bv[l * DD + r - 2 * DD];
    out[i] = v;
}

// ---------------------------------------------------------------------------
// fp16 mma.sync GEMM (R15-proven, unchanged).
// ---------------------------------------------------------------------------
__global__ __launch_bounds__(256, 2)
void gemm_f16(const __half* __restrict__ A, const __half* __restrict__ BT,
              const float* __restrict__ bias, const float* __restrict__ Rf,
              float* __restrict__ Cf, __half* __restrict__ Ch,
              int M, int N, int K, int relu)
{
    extern __shared__ __half hsm[];
    __half* As = hsm;
    __half* Bs = hsm + GSTAGES * TILE_STAGE;

    const int tid = threadIdx.x;
    const int wid = tid >> 5, lane = tid & 31;
    const int warp_m = wid >> 1;
    const int warp_n = wid & 1;
    const int g = lane >> 2;
    const int t4 = lane & 3;

    const int brow = blockIdx.y, bcol = blockIdx.x;
    const __half* Abase = A + (size_t)brow * GBM * K;
    const __half* Bbase = BT + (size_t)bcol * GBN * K;

    const uint32_t AsU = smem_u32(As);
    const uint32_t BsU = smem_u32(Bs);

    const int nk = K / GBK;

    auto stage = [&](int s, int bufi) {
        const int k0 = s * GBK;
        const uint32_t off = (uint32_t)(bufi * TILE_STAGE) * 2u;
#pragma unroll
        for (int i = 0; i < 4; i++) {
            int id = tid + i * 256;
            int r = id >> 3, c8 = id & 7;
            cp_async16(AsU + off + (uint32_t)(r * HSTRIDE + c8 * 8) * 2u,
                       Abase + (size_t)r * K + k0 + c8 * 8);
        }
#pragma unroll
        for (int i = 0; i < 4; i++) {
            int id = tid + i * 256;
            int r = id >> 3, c8 = id & 7;
            cp_async16(BsU + off + (uint32_t)(r * HSTRIDE + c8 * 8) * 2u,
                       Bbase + (size_t)r * K + k0 + c8 * 8);
        }
        cp_commit();
    };

    float acc[2][8][4];
#pragma unroll
    for (int mt = 0; mt < 2; mt++)
#pragma unroll
        for (int nt = 0; nt < 8; nt++)
#pragma unroll
            for (int j = 0; j < 4; j++) acc[mt][nt][j] = 0.0f;

#pragma unroll
    for (int s = 0; s < GSTAGES - 1; s++) {
        if (s < nk) stage(s, s); else cp_commit();
    }

    const uint32_t lrow = (uint32_t)(lane & 15) * (HSTRIDE * 2);
    const uint32_t lcol = (uint32_t)(lane >> 4) * 16;

    int rbuf = 0;
    int pbuf = GSTAGES - 1;

    for (int ks = 0; ks < nk; ks++) {
        cp_wait<GSTAGES - 2>();
        __syncthreads();

        if (ks + GSTAGES - 1 < nk) stage(ks + GSTAGES - 1, pbuf);
        else cp_commit();
        if (++pbuf == GSTAGES) pbuf = 0;

        const uint32_t abuf = AsU + (uint32_t)(rbuf * TILE_STAGE) * 2u;
        const uint32_t bbuf = BsU + (uint32_t)(rbuf * TILE_STAGE) * 2u;
        if (++rbuf == GSTAGES) rbuf = 0;

#pragma unroll
        for (int kk = 0; kk < 4; kk++) {
            const uint32_t co = (uint32_t)kk * 32 + lcol;
            uint32_t a[2][4];
#pragma unroll
            for (int mt = 0; mt < 2; mt++)
                ldsm_x4(a[mt], abuf + (uint32_t)(warp_m * 32 + mt * 16) *
                                       (HSTRIDE * 2) + lrow + co);
            uint32_t b[8][2];
#pragma unroll
            for (int np = 0; np < 4; np++) {
                uint32_t tr[4];
                ldsm_x4(tr, bbuf + (uint32_t)(warp_n * 64 + np * 16) *
                                    (HSTRIDE * 2) + lrow + co);
                b[np * 2][0] = tr[0]; b[np * 2 + 1][0] = tr[1];
                b[np * 2][1] = tr[2]; b[np * 2 + 1][1] = tr[3];
            }
#pragma unroll
            for (int mt = 0; mt < 2; mt++)
#pragma unroll
                for (int nt = 0; nt < 8; nt++)
                    mma_f16(acc[mt][nt], a[mt], b[nt]);
        }
    }

#pragma unroll
    for (int mt = 0; mt < 2; mt++) {
        const int r0 = brow * GBM + warp_m * 32 + mt * 16 + g;
#pragma unroll
        for (int nt = 0; nt < 8; nt++) {
            const int cb = bcol * GBN + warp_n * 64 + nt * 8 + t4 * 2;
            const float b0 = bias[cb], b1 = bias[cb + 1];
            float v0 = acc[mt][nt][0] + b0;
            float v1 = acc[mt][nt][1] + b1;
            float v2 = acc[mt][nt][2] + b0;
            float v3 = acc[mt][nt][3] + b1;
            if (relu) {
                v0 = fmaxf(v0, 0.f); v1 = fmaxf(v1, 0.f);
                v2 = fmaxf(v2, 0.f); v3 = fmaxf(v3, 0.f);
            }
            if (Rf) {
                float2 r0v = *reinterpret_cast<const float2*>(
                    Rf + (size_t)r0 * N + cb);
                float2 r1v = *reinterpret_cast<const float2*>(
                    Rf + (size_t)(r0 + 8) * N + cb);
                v0 += r0v.x; v1 += r0v.y;
                v2 += r1v.x; v3 += r1v.y;
            }
            if (Cf) {
                *reinterpret_cast<float2*>(Cf + (size_t)r0 * N + cb) =
                    make_float2(v0, v1);
                *reinterpret_cast<float2*>(Cf + (size_t)(r0 + 8) * N + cb) =
                    make_float2(v2, v3);
            }
            if (Ch) {
                *reinterpret_cast<__half2*>(Ch + (size_t)r0 * N + cb) =
                    __floats2half2_rn(v0, v1);
                *reinterpret_cast<__half2*>(Ch + (size_t)(r0 + 8) * N + cb) =
                    __floats2half2_rn(v2, v3);
            }
        }
    }
}

// ---------------------------------------------------------------------------
// Flash sliding-window attention (R15-proven branch-free version).
// V row-major + ldmatrix.trans. Adds residual res in epilogue.
// ---------------------------------------------------------------------------
__global__ __launch_bounds__(256, 2)
void attn_mma(const __half* __restrict__ qkv, const float* __restrict__ res,
              float* __restrict__ out)
{
    extern __shared__ __half ash[];
    __half* Ks = ash + KS_OFF;
    __half* Vs = ash + VS_OFF;

    const int c = blockIdx.x, h = blockIdx.y, b = blockIdx.z;
    const int tid = threadIdx.x;
    const int w = tid >> 5, lane = tid & 31;
    const int g = lane >> 2, t4 = lane & 3;
    const int qoff = h * 64, koff = DD + h * 64, voff = 2 * DD + h * 64;
    const int cbase = c * 128 - 128;

    const uint32_t QsU = smem_u32(ash);
    const uint32_t KsU = smem_u32(Ks);
    const uint32_t VsU = smem_u32(Vs);

#pragma unroll
    for (int i = 0; i < 4; i++) {
        int id = tid + i * 256;
        int r = id >> 3, ch = id & 7;
        uint4 v = *reinterpret_cast<const uint4*>(
            qkv + (size_t)(b * SS + c * 128 + r) * (3 * DD) + qoff + ch * 8);
        *reinterpret_cast<uint4*>(&ash[r * AQSTRIDE + ch * 8]) = v;
    }
    __syncthreads();

    const uint32_t lrow = (uint32_t)(lane & 15) * (AQSTRIDE * 2);
    const uint32_t lcol = (uint32_t)(lane >> 4) * 16;
    uint32_t qa[4][4];
#pragma unroll
    for (int ks = 0; ks < 4; ks++)
        ldsm_x4(qa[ks], QsU + (uint32_t)(w * 16) * (AQSTRIDE * 2) + lrow +
                        (uint32_t)ks * 32 + lcol);

    float o[8][4];
#pragma unroll
    for (int ch = 0; ch < 8; ch++)
#pragma unroll
        for (int j = 0; j < 4; j++) o[ch][j] = 0.0f;
    float m0 = -1e30f, m1 = -1e30f, l0 = 0.0f, l1 = 0.0f;
    const int qi0 = w * 16 + g, qi1 = qi0 + 8;

    for (int t = 0; t < 2; t++) {
        if (t) __syncthreads();
        const int kw0 = t * 192;
#pragma unroll
        for (int i = 0; i < 6; i++) {
            int id = tid + i * 256;
            int r = id >> 3, ch = id & 7;
            int kpos = cbase + kw0 + r;
            uint4 kv = make_uint4(0, 0, 0, 0), vv = make_uint4(0, 0, 0, 0);
            if (kpos >= 0 && kpos < SS) {
                const __half* rp = qkv + (size_t)(b * SS + kpos) * (3 * DD);
                kv = *reinterpret_cast<const uint4*>(rp + koff + ch * 8);
                vv = *reinterpret_cast<const uint4*>(rp + voff + ch * 8);
            }
            *reinterpret_cast<uint4*>(&Ks[r * AQSTRIDE + ch * 8]) = kv;
            *reinterpret_cast<uint4*>(&Vs[r * AQSTRIDE + ch * 8]) = vv;
        }
        __syncthreads();

        const int jb_lo = (t == 0) ? w : 12;
        const int jb_hi = (t == 0) ? 11 : (w + 16);

        for (int jb = jb_lo; jb <= jb_hi; jb++) {
            const int j0 = jb * 16 - kw0;
            float s0[4] = {0.f, 0.f, 0.f, 0.f};
            float s1[4] = {0.f, 0.f, 0.f, 0.f};
#pragma unroll
            for (int ks = 0; ks < 4; ks++) {
                uint32_t kb[4];
                ldsm_x4(kb, KsU + (uint32_t)j0 * (AQSTRIDE * 2) + lrow +
                            (uint32_t)ks * 32 + lcol);
                uint32_t b0[2] = {kb[0], kb[2]};
                uint32_t b1[2] = {kb[1], kb[3]};
                mma_f16(s0, qa[ks], b0);
                mma_f16(s1, qa[ks], b1);
            }
            const int cw = jb * 16 + 2 * t4;
            {
                auto mk = [&](float s, int cwi, int qi) -> float {
                    unsigned d = (unsigned)(cwi - qi);
                    int kp = cbase + cwi;
                    return (d <= 256u && kp >= 0 && kp < SS) ? s : -3.0e38f;
                };
                s0[0] = mk(s0[0], cw,     qi0); s0[1] = mk(s0[1], cw + 1, qi0);
                s0[2] = mk(s0[2], cw,     qi1); s0[3] = mk(s0[3], cw + 1, qi1);
                s1[0] = mk(s1[0], cw + 8, qi0); s1[1] = mk(s1[1], cw + 9, qi0);
                s1[2] = mk(s1[2], cw + 8, qi1); s1[3] = mk(s1[3], cw + 9, qi1);
            }
            float bm0 = fmaxf(fmaxf(s0[0], s0[1]), fmaxf(s1[0], s1[1]));
            float bm1 = fmaxf(fmaxf(s0[2], s0[3]), fmaxf(s1[2], s1[3]));
            bm0 = fmaxf(bm0, __shfl_xor_sync(0xffffffffu, bm0, 1));
            bm0 = fmaxf(bm0, __shfl_xor_sync(0xffffffffu, bm0, 2));
            bm1 = fmaxf(bm1, __shfl_xor_sync(0xffffffffu, bm1, 1));
            bm1 = fmaxf(bm1, __shfl_xor_sync(0xffffffffu, bm1, 2));
            float mn0 = fmaxf(m0, bm0), mn1 = fmaxf(m1, bm1);
            float sc0 = __expf(m0 - mn0), sc1 = __expf(m1 - mn1);
            m0 = mn0; m1 = mn1;
            float p00 = __expf(s0[0] - mn0), p01 = __expf(s0[1] - mn0);
            float p10 = __expf(s0[2] - mn1), p11 = __expf(s0[3] - mn1);
            float p02 = __expf(s1[0] - mn0), p03 = __expf(s1[1] - mn0);
            float p12 = __expf(s1[2] - mn1), p13 = __expf(s1[3] - mn1);
            float rs0 = (p00 + p01) + (p02 + p03);
            float rs1 = (p10 + p11) + (p12 + p13);
            rs0 += __shfl_xor_sync(0xffffffffu, rs0, 1);
            rs0 += __shfl_xor_sync(0xffffffffu, rs0, 2);
            rs1 += __shfl_xor_sync(0xffffffffu, rs1, 1);
            rs1 += __shfl_xor_sync(0xffffffffu, rs1, 2);
            l0 = l0 * sc0 + rs0;
            l1 = l1 * sc1 + rs1;

            uint32_t pa[4];
            pa[0] = h2u(p00, p01);
            pa[1] = h2u(p10, p11);
            pa[2] = h2u(p02, p03);
            pa[3] = h2u(p12, p13);

            uint32_t vb[8][2];
#pragma unroll
            for (int p = 0; p < 4; p++) {
                uint32_t tr[4];
                ldsm_x4_t(tr, VsU + (uint32_t)j0 * (AQSTRIDE * 2) + lrow +
                              (uint32_t)p * 32 + lcol);
                vb[p * 2][0] = tr[0]; vb[p * 2][1] = tr[1];
                vb[p * 2 + 1][0] = tr[2]; vb[p * 2 + 1][1] = tr[3];
            }

#pragma unroll
            for (int ch = 0; ch < 8; ch++) {
                o[ch][0] *= sc0; o[ch][1] *= sc0;
                o[ch][2] *= sc1; o[ch][3] *= sc1;
                mma_f16(o[ch], pa, vb[ch]);
            }
        }
    }

    const float inv0 = 1.0f / l0, inv1 = 1.0f / l1;
    const size_t row0 = (size_t)(b * SS + c * 128 + w * 16 + g) * DD + h * 64;
    float* op0 = out + row0;
    float* op1 = op0 + 8 * DD;
    const float* rp0 = res + row0;
    const float* rp1 = rp0 + 8 * DD;
#pragma unroll
    for (int ch = 0; ch < 8; ch++) {
        float2 a0 = *reinterpret_cast<const float2*>(rp0 + ch * 8 + 2 * t4);
        float2 a1 = *reinterpret_cast<const float2*>(rp1 + ch * 8 + 2 * t4);
        *reinterpret_cast<float2*>(op0 + ch * 8 + 2 * t4) =
            make_float2(o[ch][0] * inv0 + a0.x, o[ch][1] * inv0 + a0.y);
        *reinterpret_cast<float2*>(op1 + ch * 8 + 2 * t4) =
            make_float2(o[ch][2] * inv1 + a1.x, o[ch][3] * inv1 + a1.y);
    }
}

// ---------------------------------------------------------------------------
// LayerNorm, single-pass (sum + sumsq in one fused reduction).
// 192 threads, 1 row per CTA. Var = E[x^2] - mean^2.
// ---------------------------------------------------------------------------
__global__ __launch_bounds__(192)
void ln_kernel(const float* __restrict__ x,
               const float* __restrict__ g, const float* __restrict__ bt,
               float* __restrict__ out, __half* __restrict__ out16)
{
    __shared__ float sh[12];
    const int row = blockIdx.x;
    const int tid = threadIdx.x;
    const int lane = tid & 31, wp = tid >> 5;   // 6 warps

    float4 v = reinterpret_cast<const float4*>(x + (size_t)row * DD)[tid];

    float s = (v.x + v.y) + (v.z + v.w);
    float q = (v.x * v.x + v.y * v.y) + (v.z * v.z + v.w * v.w);
#pragma unroll
    for (int o = 16; o; o >>= 1) {
        s += __shfl_xor_sync(0xffffffffu, s, o);
        q += __shfl_xor_sync(0xffffffffu, q, o);
    }
    if (lane == 0) { sh[wp * 2] = s; sh[wp * 2 + 1] = q; }
    __syncthreads();
    float t = (lane < 12) ? sh[lane] : 0.0f;
    t += __shfl_xor_sync(0xffffffffu, t, 2);
    t += __shfl_xor_sync(0xffffffffu, t, 4);
    t += __shfl_xor_sync(0xffffffffu, t, 8);
    const float s_tot = __shfl_sync(0xffffffffu, t, 0);
    const float q_tot = __shfl_sync(0xffffffffu, t, 1);

    const float mean = s_tot * (1.0f / (float)DD);
    const float var  = q_tot * (1.0f / (float)DD) - mean * mean;
    const float inv  = rsqrtf(var + 1e-5f);

    float4 gv = reinterpret_cast<const float4*>(g)[tid];
    float4 bv = reinterpret_cast<const float4*>(bt)[tid];
    float o0 = (v.x - mean) * inv * gv.x + bv.x;
    float o1 = (v.y - mean) * inv * gv.y + bv.y;
    float o2 = (v.z - mean) * inv * gv.z + bv.z;
    float o3 = (v.w - mean) * inv * gv.w + bv.w;

    reinterpret_cast<float4*>(out + (size_t)row * DD)[tid] =
        make_float4(o0, o1, o2, o3);
    uint2 hu;
    hu.x = h2u(o0, o1);
    hu.y = h2u(o2, o3);
    reinterpret_cast<uint2*>(out16 + (size_t)row * DD)[tid] = hu;
}

// ---------------------------------------------------------------------------
// Host driver
// ---------------------------------------------------------------------------
extern "C" void kernel_launch(void* const* d_in, const int* in_sizes, int n_in,
                              void* d_out, int out_size)
{
    (void)in_sizes; (void)n_in; (void)out_size;

    const float* x0  = (const float*)d_in[0];
    const float* Wq  = (const float*)d_in[1];
    const float* bq  = (const float*)d_in[2];
    const float* Wk  = (const float*)d_in[3];
    const float* bk  = (const float*)d_in[4];
    const float* Wv  = (const float*)d_in[5];
    const float* bv  = (const float*)d_in[6];
    const float* W1  = (const float*)d_in[7];
    const float* b1  = (const float*)d_in[8];
    const float* W2  = (const float*)d_in[9];
    const float* b2  = (const float*)d_in[10];
    const float* g1  = (const float*)d_in[11];
    const float* be1 = (const float*)d_in[12];
    const float* g2  = (const float*)d_in[13];
    const float* be2 = (const float*)d_in[14];

    float* outp = (float*)d_out;

    float *xb_run, *xbb, *ab, *bqkv;
    __half *xin16, *xb16, *h16, *qkv16, *wqkv, *w1t, *w2t;
    cudaGetSymbolAddress((void**)&xb_run, g_x);
    cudaGetSymbolAddress((void**)&xbb, g_xb);
    cudaGetSymbolAddress((void**)&ab, g_a);
    cudaGetSymbolAddress((void**)&bqkv, g_bqkv);
    cudaGetSymbolAddress((void**)&xin16, g_xin16);
    cudaGetSymbolAddress((void**)&xb16, g_xb16);
    cudaGetSymbolAddress((void**)&h16, g_h16);
    cudaGetSymbolAddress((void**)&qkv16, g_qkv16);
    cudaGetSymbolAddress((void**)&wqkv, g_Wqkv);
    cudaGetSymbolAddress((void**)&w1t, g_W1T);
    cudaGetSymbolAddress((void**)&w2t, g_W2T);

    cudaFuncSetAttribute(attn_mma, cudaFuncAttributeMaxDynamicSharedMemorySize,
                         ATTN_SMEM);
    const int gemm_smem = 2 * GSTAGES * TILE_STAGE * (int)sizeof(__half);
    cudaFuncSetAttribute(gemm_f16, cudaFuncAttributeMaxDynamicSharedMemorySize,
                         gemm_smem);

    dim3 tb(32, 8);
    const size_t qkvL = (size_t)3 * DD * DD;
    dim3 gQKV(3 * DD / GBN, ROWS / GBM);
    dim3 gD(DD / GBN, ROWS / GBM);
    dim3 gF(FFD / GBN, ROWS / GBM);
    dim3 gA(NC, HH, BB);

    transpose_qkv<<<dim3(DD / 32, DD / 32, 12), tb>>>(Wq, Wk, Wv, wqkv);
    prep_bias<<<(4 * 3 * DD + 255) / 256, 256>>>(bq, bk, bv, bqkv);
    f2h_kernel<<<(ROWS * DD / 4 + 255) / 256, 256>>>(x0, xin16, ROWS * DD);

    gemm_f16<<<gQKV, 256, gemm_smem>>>(xin16, wqkv, bqkv, (const float*)0,
                                       (float*)0, qkv16, ROWS, 3 * DD, DD, 0);

    transpose_w<<<dim3(FFD / 32, DD / 32, 4), tb>>>(W1, w1t, DD, FFD,
                                                    (size_t)DD * FFD);
    transpose_w<<<dim3(DD / 32, FFD / 32, 4), tb>>>(W2, w2t, FFD, DD,
                                                    (size_t)DD * FFD);

    const float* xc = x0;
    for (int l = 0; l < 4; l++) {
        if (l > 0) {
            gemm_f16<<<gQKV, 256, gemm_smem>>>(xin16, wqkv + l * qkvL,
                                               bqkv + l * 3 * DD,
                                               (const float*)0,
                                               (float*)0, qkv16,
                                               ROWS, 3 * DD, DD, 0);
        }

        attn_mma<<<gA, 256, ATTN_SMEM>>>(qkv16, xc, ab);

        ln_kernel<<<ROWS, 192>>>(ab, g1 + l * DD, be1 + l * DD, xbb, xb16);

        gemm_f16<<<gF, 256, gemm_smem>>>(xb16, w1t + (size_t)l * DD * FFD,
                                         b1 + l * FFD, (const float*)0,
                                         (float*)0, h16, ROWS, FFD, DD, 1);
        gemm_f16<<<gD, 256, gemm_smem>>>(h16, w2t + (size_t)l * DD * FFD,
                                         b2 + l * DD, xbb,
                                         ab, (__half*)0, ROWS, DD, FFD, 0);

        float* xdst = (l == 3) ? outp : xb_run;
        ln_kernel<<<ROWS, 192>>>(ab, g2 + l * DD, be2 + l * DD, xdst, xin16);

        xc = xb_run;
    }
}